// round 6
// baseline (speedup 1.0000x reference)
#include <cuda_runtime.h>

#define BB 2
#define CC 3
#define DD 128
#define HH 128
#define WW 128
#define NSEG 11                      // 11 non-uniform h-segments (9-10 rows)
#define NWARPS (BB * DD * NSEG)      // 2816 warp tasks
#define NTHREADS 128
#define WPB (NTHREADS / 32)          // 4 warps/block
#define NBLOCKS (NWARPS / WPB)       // 704 blocks (one wave at 5+/SM)

#define W_GRAD 0.1f
#define W_TV 0.002f
#define W_BG 0.15

// 10 partial sums:
// 0:mask 1:mx 2:my 3:mz 4:(mae+mse) 5:|p| 6:|p|*m 7:gtx 8:gty 9:gtz
#define NSUMS 10
__device__ double g_sums[NSUMS];
__device__ unsigned int g_count;

__device__ __forceinline__ float warp_sum(float v) {
#pragma unroll
    for (int o = 16; o; o >>= 1) v += __shfl_down_sync(0xffffffffu, v, o);
    return v;
}

__global__ __launch_bounds__(NTHREADS, 6)   // slim body: target <= 85 regs
void loss_kernel(const float4* __restrict__ pred,
                 const float4* __restrict__ targ,
                 const float4* __restrict__ mask,
                 float* __restrict__ out) {
    const int wid  = threadIdx.x >> 5;
    const int lane = threadIdx.x & 31;
    const int gwarp = blockIdx.x * WPB + wid;

    // task decode: gwarp -> (b, d, seg)
    const int seg = gwarp % NSEG;
    const int bd  = gwarp / NSEG;
    const int d   = bd & (DD - 1);
    const int b   = bd >> 7;             // / DD
    const int h0  = (seg * HH) / NSEG;
    const int h1  = ((seg + 1) * HH) / NSEG;

    const float dv  = (d < DD - 1) ? 1.0f : 0.0f;     // dx validity
    const float ze  = (lane < 31) ? 1.0f : 0.0f;      // w=127 edge

    const int ROWQ = WW / 4;                          // 32 float4 per row
    const int CSTR = DD * HH * ROWQ;                  // channel stride (float4)
    const int dskip = (d < DD - 1) ? HH * ROWQ : 0;   // d+1 plane (clamped)

    int mo = ((b * DD + d) * HH + h0) * ROWQ + lane;
    int po = (((b * CC) * DD + d) * HH + h0) * ROWQ + lane;

    // previous-h state: RAW diff = p - t and RAW p (no mask products needed:
    // every use is multiplied by min(m, m_prev) which is 1 only when both
    // masks are 1, making raw == masked; 0 kills the term otherwise).
    float4 pm = make_float4(0.f, 0.f, 0.f, 0.f);
    float4 pdf[CC], ppr[CC];
#pragma unroll
    for (int c = 0; c < CC; c++) {
        pdf[c] = make_float4(0.f, 0.f, 0.f, 0.f);
        ppr[c] = make_float4(0.f, 0.f, 0.f, 0.f);
    }

    if (h0 > 0) {  // preload row h0-1 to seed the y-gradient (raw values)
        pm = mask[mo - ROWQ];
#pragma unroll
        for (int c = 0; c < CC; c++) {
            float4 p = pred[po + c * CSTR - ROWQ];
            float4 t = targ[po + c * CSTR - ROWQ];
            pdf[c] = make_float4(p.x - t.x, p.y - t.y, p.z - t.z, p.w - t.w);
            ppr[c] = p;
        }
    }

    float s_m = 0.f, s_mx = 0.f, s_my = 0.f, s_mz = 0.f;
    float s_mm = 0.f, s_ba = 0.f, s_bm = 0.f;
    float s_gtx = 0.f, s_gty = 0.f, s_gtz = 0.f;

    for (int hh = h0; hh < h1; hh++) {
        const float4 m  = mask[mo];
        const float4 md = mask[mo + dskip];

        const float4 mx4 = make_float4(fminf(m.x, md.x) * dv, fminf(m.y, md.y) * dv,
                                       fminf(m.z, md.z) * dv, fminf(m.w, md.w) * dv);
        const float4 my4 = make_float4(fminf(m.x, pm.x), fminf(m.y, pm.y),
                                       fminf(m.z, pm.z), fminf(m.w, pm.w));
        const float mnx = __shfl_down_sync(0xffffffffu, m.x, 1);
        const float mz0 = fminf(m.x, m.y), mz1 = fminf(m.y, m.z);
        const float mz2 = fminf(m.z, m.w), mz3 = fminf(m.w, mnx) * ze;

        s_m  += (m.x + m.y) + (m.z + m.w);
        s_mx += (mx4.x + mx4.y) + (mx4.z + mx4.w);
        s_my += (my4.x + my4.y) + (my4.z + my4.w);
        s_mz += (mz0 + mz1) + (mz2 + mz3);

#pragma unroll
        for (int c = 0; c < CC; c++) {
            const float4 p  = pred[po + c * CSTR];
            const float4 t  = targ[po + c * CSTR];
            const float4 pd = pred[po + c * CSTR + dskip];
            const float4 td = targ[po + c * CSTR + dskip];

            const float4 df = make_float4(p.x - t.x, p.y - t.y,
                                          p.z - t.z, p.w - t.w);      // raw diff
            const float4 dfd = make_float4(pd.x - td.x, pd.y - td.y,
                                           pd.z - td.z, pd.w - td.w); // raw diff d+1

            // (|diff| + diff^2) * m  (mae+mse share denominator)
            s_mm += fmaf(df.x, df.x, fabsf(df.x)) * m.x
                  + fmaf(df.y, df.y, fabsf(df.y)) * m.y
                  + fmaf(df.z, df.z, fabsf(df.z)) * m.z
                  + fmaf(df.w, df.w, fabsf(df.w)) * m.w;
            // |p|*(1-m) = sum|p| - sum|p|*m
            const float ax = fabsf(p.x), ay = fabsf(p.y),
                        az = fabsf(p.z), aw = fabsf(p.w);
            s_ba += (ax + ay) + (az + aw);
            s_bm += ax * m.x + ay * m.y + az * m.z + aw * m.w;

            // grad (0.1) + tv (0.002), raw differences, masked once
            s_gtx += fmaf(W_TV, fabsf(pd.x - p.x), W_GRAD * fabsf(dfd.x - df.x)) * mx4.x
                   + fmaf(W_TV, fabsf(pd.y - p.y), W_GRAD * fabsf(dfd.y - df.y)) * mx4.y
                   + fmaf(W_TV, fabsf(pd.z - p.z), W_GRAD * fabsf(dfd.z - df.z)) * mx4.z
                   + fmaf(W_TV, fabsf(pd.w - p.w), W_GRAD * fabsf(dfd.w - df.w)) * mx4.w;

            s_gty += fmaf(W_TV, fabsf(p.x - ppr[c].x), W_GRAD * fabsf(df.x - pdf[c].x)) * my4.x
                   + fmaf(W_TV, fabsf(p.y - ppr[c].y), W_GRAD * fabsf(df.y - pdf[c].y)) * my4.y
                   + fmaf(W_TV, fabsf(p.z - ppr[c].z), W_GRAD * fabsf(df.z - pdf[c].z)) * my4.z
                   + fmaf(W_TV, fabsf(p.w - ppr[c].w), W_GRAD * fabsf(df.w - pdf[c].w)) * my4.w;

            const float dnx = __shfl_down_sync(0xffffffffu, df.x, 1);
            const float pnx = __shfl_down_sync(0xffffffffu, p.x, 1);
            s_gtz += fmaf(W_TV, fabsf(p.y - p.x), W_GRAD * fabsf(df.y - df.x)) * mz0
                   + fmaf(W_TV, fabsf(p.z - p.y), W_GRAD * fabsf(df.z - df.y)) * mz1
                   + fmaf(W_TV, fabsf(p.w - p.z), W_GRAD * fabsf(df.w - df.z)) * mz2
                   + fmaf(W_TV, fabsf(pnx - p.w), W_GRAD * fabsf(dnx - df.w)) * mz3;

            pdf[c] = df;
            ppr[c] = p;
        }
        pm = m;
        mo += ROWQ; po += ROWQ;
    }

    // ---- block-level reduction: warp -> smem -> NSUMS atomics per block ----
    __shared__ float red[WPB][NSUMS];
    float vals[NSUMS] = {s_m, s_mx, s_my, s_mz, s_mm, s_ba, s_bm,
                         s_gtx, s_gty, s_gtz};
#pragma unroll
    for (int i = 0; i < NSUMS; i++) {
        const float r = warp_sum(vals[i]);
        if (lane == 0) red[wid][i] = r;
    }
    __syncthreads();

    if (threadIdx.x < NSUMS) {
        float acc = red[0][threadIdx.x];
#pragma unroll
        for (int w = 1; w < WPB; w++) acc += red[w][threadIdx.x];
        atomicAdd(&g_sums[threadIdx.x], (double)acc);
        __threadfence();
    }
    __syncthreads();

    // ---- last block finalizes + resets scratch (graph-replay determinism) ----
    if (threadIdx.x == 0) {
        const unsigned int old = atomicAdd(&g_count, 1u);
        if (old == NBLOCKS - 1) {
            double s[NSUMS];
#pragma unroll
            for (int i = 0; i < NSUMS; i++) s[i] = atomicAdd(&g_sums[i], 0.0);
            const double e = 1e-8;
            const double sm  = s[0], smx = s[1], smy = s[2], smz = s[3];
            const double mm  = s[4];
            const double bg  = s[5] - s[6];     // sum|p| - sum|p|*m
            const double gtx = s[7], gty = s[8], gtz = s[9];
            const double inv = (double)BB * DD * HH * WW - sm;

            const double r = mm / (sm * 3.0 + e)          // mae + mse
                           + gtx / (smx * 3.0 + e)
                           + gty / (smy * 3.0 + e)
                           + gtz / (smz * 3.0 + e)
                           + W_BG * (bg / (inv * 3.0 + e));
            out[0] = (float)r;

#pragma unroll
            for (int i = 0; i < NSUMS; i++) g_sums[i] = 0.0;
            g_count = 0u;
        }
    }
}

extern "C" void kernel_launch(void* const* d_in, const int* in_sizes, int n_in,
                              void* d_out, int out_size) {
    // mask is the smallest input; pred/target keep their relative order
    int mi = 0;
    for (int i = 1; i < n_in; i++)
        if (in_sizes[i] < in_sizes[mi]) mi = i;
    int others[2], k = 0;
    for (int i = 0; i < 3; i++)
        if (i != mi) others[k++] = i;

    const float4* pred = (const float4*)d_in[others[0]];
    const float4* targ = (const float4*)d_in[others[1]];
    const float4* mask = (const float4*)d_in[mi];

    loss_kernel<<<NBLOCKS, NTHREADS>>>(pred, targ, mask, (float*)d_out);
}

// round 7
// speedup vs baseline: 1.2596x; 1.2596x over previous
#include <cuda_runtime.h>

#define BB 2
#define CC 3
#define DD 128
#define HH 128
#define WW 128
#define NTASKS (BB * DD * HH)        // 32768 row tasks (b,d,h)
#define NTHREADS 128
#define WPB (NTHREADS / 32)          // 4 warps/block
#define NBLOCKS (148 * 7)            // persistent: exactly 7 blocks/SM
#define TOTW (NBLOCKS * WPB)         // 4144 resident warps

#define W_GRAD 0.1f
#define W_TV 0.002f
#define W_BG 0.15

// 10 partial sums:
// 0:mask 1:mx 2:my 3:mz 4:(mae+mse) 5:|p| 6:|p|*m 7:gtx 8:gty 9:gtz
#define NSUMS 10
__device__ double g_sums[NSUMS];
__device__ unsigned int g_count;

__device__ __forceinline__ float warp_sum(float v) {
#pragma unroll
    for (int o = 16; o; o >>= 1) v += __shfl_down_sync(0xffffffffu, v, o);
    return v;
}

__global__ __launch_bounds__(NTHREADS, 7)   // cap regs at 73 -> 7 blocks/SM
void loss_kernel(const float4* __restrict__ pred,
                 const float4* __restrict__ targ,
                 const float4* __restrict__ mask,
                 float* __restrict__ out) {
    const int wid   = threadIdx.x >> 5;
    const int lane  = threadIdx.x & 31;
    const int gwarp = blockIdx.x * WPB + wid;

    const float ze = (lane < 31) ? 1.0f : 0.0f;       // w=127 edge
    const int ROWQ = WW / 4;                          // 32 float4 per row
    const int CSTR = DD * HH * ROWQ;                  // channel stride (float4)

    float s_m = 0.f, s_mx = 0.f, s_my = 0.f, s_mz = 0.f;
    float s_mm = 0.f, s_ba = 0.f, s_bm = 0.f;
    float s_gtx = 0.f, s_gty = 0.f, s_gtz = 0.f;

    // Persistent grid-stride over independent row tasks. No carried state:
    // y-gradient is computed FORWARD (row h vs h+1); the h+1 / d+1 reloads
    // are L2/L1 hits because neighboring tasks run concurrently.
    for (int task = gwarp; task < NTASKS; task += TOTW) {
        const int h  = task & (HH - 1);
        const int bd = task >> 7;
        const int d  = bd & (DD - 1);
        const int b  = bd >> 7;

        const float dv = (d < DD - 1) ? 1.0f : 0.0f;  // dx validity
        const float hv = (h < HH - 1) ? 1.0f : 0.0f;  // dy validity
        const int dskip = (d < DD - 1) ? HH * ROWQ : 0;
        const int hskip = (h < HH - 1) ? ROWQ : 0;

        const int mo = (bd * HH + h) * ROWQ + lane;
        const int po = (((b * CC) * DD + d) * HH + h) * ROWQ + lane;

        const float4 m  = mask[mo];
        const float4 md = mask[mo + dskip];
        const float4 mh = mask[mo + hskip];

        const float4 mx4 = make_float4(fminf(m.x, md.x) * dv, fminf(m.y, md.y) * dv,
                                       fminf(m.z, md.z) * dv, fminf(m.w, md.w) * dv);
        const float4 my4 = make_float4(fminf(m.x, mh.x) * hv, fminf(m.y, mh.y) * hv,
                                       fminf(m.z, mh.z) * hv, fminf(m.w, mh.w) * hv);
        const float mnx = __shfl_down_sync(0xffffffffu, m.x, 1);
        const float mz0 = fminf(m.x, m.y), mz1 = fminf(m.y, m.z);
        const float mz2 = fminf(m.z, m.w), mz3 = fminf(m.w, mnx) * ze;

        s_m  += (m.x + m.y) + (m.z + m.w);
        s_mx += (mx4.x + mx4.y) + (mx4.z + mx4.w);
        s_my += (my4.x + my4.y) + (my4.z + my4.w);
        s_mz += (mz0 + mz1) + (mz2 + mz3);

#pragma unroll
        for (int c = 0; c < CC; c++) {
            const float4 p  = pred[po + c * CSTR];
            const float4 t  = targ[po + c * CSTR];
            const float4 pd = pred[po + c * CSTR + dskip];
            const float4 td = targ[po + c * CSTR + dskip];
            const float4 ph = pred[po + c * CSTR + hskip];
            const float4 th = targ[po + c * CSTR + hskip];

            // raw diffs — masking by min(m, m_nbr) makes products redundant
            const float4 df  = make_float4(p.x - t.x, p.y - t.y,
                                           p.z - t.z, p.w - t.w);
            const float4 dfd = make_float4(pd.x - td.x, pd.y - td.y,
                                           pd.z - td.z, pd.w - td.w);
            const float4 dfh = make_float4(ph.x - th.x, ph.y - th.y,
                                           ph.z - th.z, ph.w - th.w);

            // (|diff| + diff^2) * m  (mae+mse share denominator)
            s_mm += fmaf(df.x, df.x, fabsf(df.x)) * m.x
                  + fmaf(df.y, df.y, fabsf(df.y)) * m.y
                  + fmaf(df.z, df.z, fabsf(df.z)) * m.z
                  + fmaf(df.w, df.w, fabsf(df.w)) * m.w;
            // |p|*(1-m) = sum|p| - sum|p|*m
            const float ax = fabsf(p.x), ay = fabsf(p.y),
                        az = fabsf(p.z), aw = fabsf(p.w);
            s_ba += (ax + ay) + (az + aw);
            s_bm += ax * m.x + ay * m.y + az * m.z + aw * m.w;

            // grad (0.1) + tv (0.002): shared denominators, weights folded
            s_gtx += fmaf(W_TV, fabsf(pd.x - p.x), W_GRAD * fabsf(dfd.x - df.x)) * mx4.x
                   + fmaf(W_TV, fabsf(pd.y - p.y), W_GRAD * fabsf(dfd.y - df.y)) * mx4.y
                   + fmaf(W_TV, fabsf(pd.z - p.z), W_GRAD * fabsf(dfd.z - df.z)) * mx4.z
                   + fmaf(W_TV, fabsf(pd.w - p.w), W_GRAD * fabsf(dfd.w - df.w)) * mx4.w;

            s_gty += fmaf(W_TV, fabsf(ph.x - p.x), W_GRAD * fabsf(dfh.x - df.x)) * my4.x
                   + fmaf(W_TV, fabsf(ph.y - p.y), W_GRAD * fabsf(dfh.y - df.y)) * my4.y
                   + fmaf(W_TV, fabsf(ph.z - p.z), W_GRAD * fabsf(dfh.z - df.z)) * my4.z
                   + fmaf(W_TV, fabsf(ph.w - p.w), W_GRAD * fabsf(dfh.w - df.w)) * my4.w;

            const float dnx = __shfl_down_sync(0xffffffffu, df.x, 1);
            const float pnx = __shfl_down_sync(0xffffffffu, p.x, 1);
            s_gtz += fmaf(W_TV, fabsf(p.y - p.x), W_GRAD * fabsf(df.y - df.x)) * mz0
                   + fmaf(W_TV, fabsf(p.z - p.y), W_GRAD * fabsf(df.z - df.y)) * mz1
                   + fmaf(W_TV, fabsf(p.w - p.z), W_GRAD * fabsf(df.w - df.z)) * mz2
                   + fmaf(W_TV, fabsf(pnx - p.w), W_GRAD * fabsf(dnx - df.w)) * mz3;
        }
    }

    // ---- block-level reduction: warp -> smem -> NSUMS atomics per block ----
    __shared__ float red[WPB][NSUMS];
    float vals[NSUMS] = {s_m, s_mx, s_my, s_mz, s_mm, s_ba, s_bm,
                         s_gtx, s_gty, s_gtz};
#pragma unroll
    for (int i = 0; i < NSUMS; i++) {
        const float r = warp_sum(vals[i]);
        if (lane == 0) red[wid][i] = r;
    }
    __syncthreads();

    if (threadIdx.x < NSUMS) {
        float acc = red[0][threadIdx.x];
#pragma unroll
        for (int w = 1; w < WPB; w++) acc += red[w][threadIdx.x];
        atomicAdd(&g_sums[threadIdx.x], (double)acc);
        __threadfence();
    }
    __syncthreads();

    // ---- last block finalizes + resets scratch (graph-replay determinism) ----
    if (threadIdx.x == 0) {
        const unsigned int old = atomicAdd(&g_count, 1u);
        if (old == NBLOCKS - 1) {
            double s[NSUMS];
#pragma unroll
            for (int i = 0; i < NSUMS; i++) s[i] = atomicAdd(&g_sums[i], 0.0);
            const double e = 1e-8;
            const double sm  = s[0], smx = s[1], smy = s[2], smz = s[3];
            const double mm  = s[4];
            const double bg  = s[5] - s[6];     // sum|p| - sum|p|*m
            const double gtx = s[7], gty = s[8], gtz = s[9];
            const double inv = (double)BB * DD * HH * WW - sm;

            const double r = mm / (sm * 3.0 + e)          // mae + mse
                           + gtx / (smx * 3.0 + e)
                           + gty / (smy * 3.0 + e)
                           + gtz / (smz * 3.0 + e)
                           + W_BG * (bg / (inv * 3.0 + e));
            out[0] = (float)r;

#pragma unroll
            for (int i = 0; i < NSUMS; i++) g_sums[i] = 0.0;
            g_count = 0u;
        }
    }
}

extern "C" void kernel_launch(void* const* d_in, const int* in_sizes, int n_in,
                              void* d_out, int out_size) {
    // mask is the smallest input; pred/target keep their relative order
    int mi = 0;
    for (int i = 1; i < n_in; i++)
        if (in_sizes[i] < in_sizes[mi]) mi = i;
    int others[2], k = 0;
    for (int i = 0; i < 3; i++)
        if (i != mi) others[k++] = i;

    const float4* pred = (const float4*)d_in[others[0]];
    const float4* targ = (const float4*)d_in[others[1]];
    const float4* mask = (const float4*)d_in[mi];

    loss_kernel<<<NBLOCKS, NTHREADS>>>(pred, targ, mask, (float*)d_out);
}